// round 9
// baseline (speedup 1.0000x reference)
#include <cuda_runtime.h>

// Shapes fixed by the reference
#define BB 16
#define TT 8192
#define CC 512
#define YY 256
#define C4 (CC / 4)              // 128 float4 lanes per frame row
#define NSPAN (BB * YY)          // 4096
#define FPB 128                  // frames per pool block
#define BLK_PER_B (TT / FPB)     // 64
#define NBLK (BB * BLK_PER_B)    // 1024 (single wave: <= 1184 resident)

// Span metadata (allocation-free __device__ globals)
__device__ int   g_end[NSPAN];   // clipped inclusive cumsum per span
__device__ float g_inv[NSPAN];   // 1/cnt (0 if empty)

// ---------------------------------------------------------------------------
// Setup: blocks 0..15 compute the per-batch cumsum -> clipped ends + 1/cnt;
// ALL 64 blocks cooperatively zero the 8MB output (required: empty spans and
// the RED-accumulated boundary spans need exact-zero initial values).
// grid = 64, block = 256
// ---------------------------------------------------------------------------
__global__ void __launch_bounds__(YY)
setup_kernel(const int* __restrict__ dur, float* __restrict__ out) {
    const int y = threadIdx.x;
    if (blockIdx.x < BB) {
        __shared__ int s[YY];
        const int b = blockIdx.x;
        const int v = dur[b * YY + y];
        s[y] = v;
        __syncthreads();
        #pragma unroll
        for (int off = 1; off < YY; off <<= 1) {
            int add = (y >= off) ? s[y - off] : 0;
            __syncthreads();
            s[y] += add;
            __syncthreads();
        }
        const int incl = s[y];
        const int st  = min(incl - v, TT);
        const int en  = min(incl, TT);
        const int cnt = en - st;
        g_end[b * YY + y] = en;
        g_inv[b * YY + y] = (cnt > 0) ? (1.0f / (float)cnt) : 0.0f;
    }
    // zero output: 64 blocks x 256 threads over NSPAN*C4 = 524288 float4
    float4* o4 = reinterpret_cast<float4*>(out);
    const float4 z = make_float4(0.f, 0.f, 0.f, 0.f);
    const int stride = 64 * YY;
    for (int i = blockIdx.x * YY + y; i < NSPAN * C4; i += stride) o4[i] = z;
}

// ---------------------------------------------------------------------------
// Pool: frame-ordered static decomposition. Block k streams the contiguous
// frame tile [k*FPB, (k+1)*FPB) of its batch (256 KB, perfectly sequential),
// walking the spans that overlap it. 128 threads = one float4 channel lane
// each -> contiguous 2048B per frame row; unroll-4 / 4 accumulators (R3 loop).
// Whole spans -> direct store; boundary spans (<= 2 partials, cnt<64<FPB)
// -> red.global.add.v4.f32 into the zeroed, L2-resident output
// (2 commutative partials -> bitwise deterministic).
// ---------------------------------------------------------------------------
__global__ void __launch_bounds__(128, 8)
pool_kernel(const float* __restrict__ emg, float* __restrict__ out) {
    __shared__ int   sh_end[YY];
    __shared__ float sh_inv[YY];
    const int tid = threadIdx.x;           // 0..127
    const int blk = blockIdx.x;
    const int b   = blk >> 6;              // BLK_PER_B == 64
    const int t0  = (blk & 63) * FPB;      // tile start (local frame)
    const int t1  = t0 + FPB;

    sh_end[tid]       = g_end[b * YY + tid];
    sh_end[tid + 128] = g_end[b * YY + tid + 128];
    sh_inv[tid]       = g_inv[b * YY + tid];
    sh_inv[tid + 128] = g_inv[b * YY + tid + 128];
    __syncthreads();

    // first span j with end > t0
    int lo = 0, hi = YY;
    while (lo < hi) {
        const int mid = (lo + hi) >> 1;
        if (sh_end[mid] <= t0) lo = mid + 1; else hi = mid;
    }
    int j = lo;
    int t = t0;

    const float4* base = reinterpret_cast<const float4*>(emg)
                         + (size_t)b * TT * C4 + tid;

    while (j < YY) {
        const int e       = sh_end[j];
        const int seg_end = min(e, t1);

        if (seg_end > t) {
            const float4* p = base + (size_t)t * C4;
            float4 a0 = make_float4(0.f, 0.f, 0.f, 0.f);
            float4 a1 = a0, a2 = a0, a3 = a0;
            const int n = seg_end - t;

            int k = 0;
            for (; k + 4 <= n; k += 4) {
                const float4 v0 = p[0 * C4];
                const float4 v1 = p[1 * C4];
                const float4 v2 = p[2 * C4];
                const float4 v3 = p[3 * C4];
                a0.x += v0.x; a0.y += v0.y; a0.z += v0.z; a0.w += v0.w;
                a1.x += v1.x; a1.y += v1.y; a1.z += v1.z; a1.w += v1.w;
                a2.x += v2.x; a2.y += v2.y; a2.z += v2.z; a2.w += v2.w;
                a3.x += v3.x; a3.y += v3.y; a3.z += v3.z; a3.w += v3.w;
                p += 4 * C4;
            }
            for (; k < n; k++) {
                const float4 vv = p[0];
                a0.x += vv.x; a0.y += vv.y; a0.z += vv.z; a0.w += vv.w;
                p += C4;
            }

            const float inv = sh_inv[j];
            float4 r;
            r.x = ((a0.x + a1.x) + (a2.x + a3.x)) * inv;
            r.y = ((a0.y + a1.y) + (a2.y + a3.y)) * inv;
            r.z = ((a0.z + a1.z) + (a2.z + a3.z)) * inv;
            r.w = ((a0.w + a1.w) + (a2.w + a3.w)) * inv;

            const int start = j ? sh_end[j - 1] : 0;
            float* dst = out + ((size_t)b * YY + j) * CC + tid * 4;
            if (start >= t0 && e <= t1) {
                *reinterpret_cast<float4*>(dst) = r;   // whole span in tile
            } else {
                asm volatile("red.global.add.v4.f32 [%0], {%1, %2, %3, %4};"
                             :: "l"(dst), "f"(r.x), "f"(r.y), "f"(r.z), "f"(r.w)
                             : "memory");
            }
        }

        if (e >= t1) break;   // this span reaches/overruns the tile end
        t = seg_end;
        j++;
    }
}

extern "C" void kernel_launch(void* const* d_in, const int* in_sizes, int n_in,
                              void* d_out, int out_size) {
    const float* emg = (const float*)d_in[0];
    const int*   dur = (const int*)d_in[1];
    float*       out = (float*)d_out;

    setup_kernel<<<64, YY>>>(dur, out);
    pool_kernel<<<NBLK, 128>>>(emg, out);
}

// round 10
// speedup vs baseline: 1.0472x; 1.0472x over previous
#include <cuda_runtime.h>

// Shapes fixed by the reference
#define BB 16
#define TT 8192
#define CC 512
#define YY 256
#define C4 (CC / 4)            // 128 float4 lanes per frame row
#define NSPAN (BB * YY)        // 4096
#define GRID_POOL (148 * 8)    // 8 blocks/SM: RF-limited optimum (64 regs)

// Work-stealing state (module-static, self-restoring each launch)
__device__ int g_next = GRID_POOL;
__device__ int g_done = 0;

// ---------------------------------------------------------------------------
// Single fused persistent kernel.
// Each block steals whole spans (b, y) in span order (best measured DRAM
// page locality). Per span:
//   0. thread 0 prefetches the NEXT span id (atomic hidden under frame loop)
//   1. threads 0..63 reduce durations[b, 0..y-1] -> start; dur[b,y] -> cnt
//      (warp REDUX.SUM, durations row is L1-resident)
//   2. 128 threads, one float4 channel lane each -> contiguous 2048B per
//      frame row; unroll-4, 4 independent accumulators, plain loads —
//      the R3-proven 76%-DRAM streaming loop, byte-identical. DO NOT TOUCH.
// Last block restores the steal counters (graph-replay safe, deterministic).
// ---------------------------------------------------------------------------
__global__ void __launch_bounds__(128, 8)
pool_fused_kernel(const float* __restrict__ emg,
                  const int*   __restrict__ dur,
                  float*       __restrict__ out) {
    __shared__ int sh[4];            // [0],[1] warp sums, [2] cnt, [3] next id
    const int tid = threadIdx.x;     // 0..127

    int by = blockIdx.x;
    while (by < NSPAN) {
        // ---- prefetch next span id ----
        if (tid == 0) sh[3] = atomicAdd(&g_next, 1);

        const int b = by >> 8;       // YY == 256
        const int y = by & 255;

        // ---- span metadata: start = sum_{j<y} dur[b,j], cnt = dur[b,y] ----
        if (tid < 64) {
            const int4 v = __ldg(reinterpret_cast<const int4*>(dur) + b * 64 + tid);
            const int base = tid * 4;
            int s = 0;
            if (base + 0 < y) s += v.x;
            if (base + 1 < y) s += v.y;
            if (base + 2 < y) s += v.z;
            if (base + 3 < y) s += v.w;
            if ((y >> 2) == tid) {
                int c;
                switch (y & 3) {
                    case 0:  c = v.x; break;
                    case 1:  c = v.y; break;
                    case 2:  c = v.z; break;
                    default: c = v.w; break;
                }
                sh[2] = c;
            }
            s = __reduce_add_sync(0xffffffffu, s);   // REDUX.SUM
            if ((tid & 31) == 0) sh[tid >> 5] = s;
        }
        __syncthreads();

        const int start_raw = sh[0] + sh[1];
        const int st  = min(start_raw, TT);
        const int en  = min(start_raw + sh[2], TT);
        const int cnt = en - st;

        // ---- mean-pool cnt frames (R3 loop, byte-identical) ----
        const float4* p = reinterpret_cast<const float4*>(emg)
                          + ((size_t)b * TT + st) * C4 + tid;

        float4 a0 = make_float4(0.f, 0.f, 0.f, 0.f);
        float4 a1 = a0, a2 = a0, a3 = a0;

        int t = 0;
        for (; t + 4 <= cnt; t += 4) {
            const float4 v0 = p[0 * C4];
            const float4 v1 = p[1 * C4];
            const float4 v2 = p[2 * C4];
            const float4 v3 = p[3 * C4];
            a0.x += v0.x; a0.y += v0.y; a0.z += v0.z; a0.w += v0.w;
            a1.x += v1.x; a1.y += v1.y; a1.z += v1.z; a1.w += v1.w;
            a2.x += v2.x; a2.y += v2.y; a2.z += v2.z; a2.w += v2.w;
            a3.x += v3.x; a3.y += v3.y; a3.z += v3.z; a3.w += v3.w;
            p += 4 * C4;
        }
        for (; t < cnt; t++) {
            const float4 vv = p[0];
            a0.x += vv.x; a0.y += vv.y; a0.z += vv.z; a0.w += vv.w;
            p += C4;
        }

        const float inv = (cnt > 0) ? (1.0f / (float)cnt) : 0.0f;
        float4 r;
        r.x = ((a0.x + a1.x) + (a2.x + a3.x)) * inv;
        r.y = ((a0.y + a1.y) + (a2.y + a3.y)) * inv;
        r.z = ((a0.z + a1.z) + (a2.z + a3.z)) * inv;
        r.w = ((a0.w + a1.w) + (a2.w + a3.w)) * inv;

        reinterpret_cast<float4*>(out)[(size_t)by * C4 + tid] = r;

        // ---- consume prefetched span id ----
        __syncthreads();
        by = sh[3];
        __syncthreads();
    }

    // ---- last block restores steal state for the next (graph) launch ----
    if (tid == 0) {
        const int d = atomicAdd(&g_done, 1);
        if (d == GRID_POOL - 1) {
            g_next = GRID_POOL;
            g_done = 0;
            __threadfence();
        }
    }
}

extern "C" void kernel_launch(void* const* d_in, const int* in_sizes, int n_in,
                              void* d_out, int out_size) {
    const float* emg = (const float*)d_in[0];
    const int*   dur = (const int*)d_in[1];
    float*       out = (float*)d_out;

    pool_fused_kernel<<<GRID_POOL, 128>>>(emg, dur, out);
}